// round 7
// baseline (speedup 1.0000x reference)
#include <cuda_runtime.h>
#include <stdint.h>

// Problem constants (fixed by the dataset)
#define NBATCH 16
#define TT     2048
#define SS     2048
#define HH     64
#define KSEL   64

__device__ __forceinline__ unsigned long long umax64(unsigned long long a, unsigned long long b) {
    return a > b ? a : b;
}
__device__ __forceinline__ unsigned long long umin64(unsigned long long a, unsigned long long b) {
    return a < b ? a : b;
}

// key = (sortable_score << 8) | (127 - expanded_idx)
// numeric DESC order == desc by score, ties broken by ascending index (lax.top_k)
__device__ __forceinline__ unsigned long long enc_key(float s, int idx) {
    unsigned int u  = __float_as_uint(s);
    unsigned int su = (u & 0x80000000u) ? ~u : (u | 0x80000000u);
    return ((unsigned long long)su << 8) | (unsigned long long)(127 - idx);
}

// inverse of enc_key's score field
__device__ __forceinline__ float dec_score(unsigned long long key) {
    unsigned int su = (unsigned int)(key >> 8);
    unsigned int u  = (su & 0x80000000u) ? (su & 0x7FFFFFFFu) : ~su;
    return __uint_as_float(u);
}

__global__ __launch_bounds__(64)
void tree_attn_kernel(const float* __restrict__ q,
                      const float* __restrict__ kmat,
                      const float* __restrict__ v,
                      float* __restrict__ out)
{
    __shared__ float              sc_odd[64];  // fresh (odd-child) scores
    __shared__ unsigned long long xkey[64];    // cross-warp sort exchange
    __shared__ int                zpar[64];    // parent z values
    __shared__ float              spar[64];    // parent scores
    __shared__ int                pos_s[64];
    __shared__ float              pvec[64];
    __shared__ float              red[4];

    const int row  = blockIdx.x;
    const int n    = row >> 11;
    const int t    = row & (TT - 1);
    const float tsrc = (float)(t + 1);

    const int g    = threadIdx.x;   // 0..63
    const int lane = g & 31;
    const int l16  = g & 15;
    const int hwg  = g >> 4;        // half-warp 0..3
    const unsigned gm = 0xFFFFu << (lane & 16);   // 16-lane group shfl mask

    const float* kbase = kmat + (size_t)n * SS * HH;
    const float4 q4 = ((const float4*)(q + ((size_t)(n * TT + t)) * HH))[l16];

    unsigned long long key = 0;  // selection key (score packed in bits [8,40))
    int zsel = 0;

    // R3-verbatim scoring reduction tree (numerics pinned: this tree's rounding
    // bit-matches the reference einsum; do NOT change the reduction order).
    #define SCORE_FRESH(POS, CIDX)                                            \
        {                                                                     \
            const float4* krow = (const float4*)(kbase + (size_t)(POS) * HH); \
            float4 k4 = krow[l16];                                            \
            float part = q4.x * k4.x + q4.y * k4.y + q4.z * k4.z + q4.w * k4.w;\
            part += __shfl_xor_sync(gm, part, 1);                             \
            part += __shfl_xor_sync(gm, part, 2);                             \
            part += __shfl_xor_sync(gm, part, 4);                             \
            part += __shfl_xor_sync(gm, part, 8);                             \
            if (l16 == 0) sc_odd[CIDX] = part;                                \
        }

    // Odd child vs even sibling: if both round to the same token, the fresh
    // score would be bit-equal to the parent's score -> reuse, skip LDG+SHFL.
    #define SCORE_ODD(ZP, SP, R, CIDX)                                        \
        {                                                                     \
            int posO = min((int)rintf((float)(2 * (ZP) + 1) * (R)), SS - 1);  \
            int posE = min((int)rintf((float)(2 * (ZP)) * (R)), SS - 1);      \
            if (posO == posE) {                                               \
                if (l16 == 0) sc_odd[CIDX] = (SP);                            \
            } else {                                                          \
                SCORE_FRESH(posO, CIDX)                                       \
            }                                                                 \
        }

    // ---------------- iteration 0: 32 fresh candidates, w2=32 ----------------
    {
        const float r = tsrc * (1.0f / 32.0f);
        for (int c = hwg; c < 32; c += 4) {
            int pos = min((int)rintf((float)c * r), SS - 1);
            SCORE_FRESH(pos, c)
        }
        __syncthreads();
        if (g < 32) {   // warp0: 15-stage desc bitonic sort of 32
            key = enc_key(sc_odd[lane], lane);   // expanded idx == z at level 0
            #pragma unroll
            for (int kk = 2; kk <= 32; kk <<= 1)
                #pragma unroll
                for (int j = kk >> 1; j > 0; j >>= 1) {
                    unsigned long long p = __shfl_xor_sync(0xffffffffu, key, j);
                    bool mx = (((lane & j) == 0) == ((lane & kk) == 0));
                    key = mx ? umax64(key, p) : umin64(key, p);
                }
            zsel = 127 - (int)(key & 0xFFu);
        }
        __syncthreads();   // sc_odd reuse barrier
    }

    // ---------------- iteration 1: 32 parents -> keep all 64, w2=64 ----------
    {
        if (g < 32) { zpar[g] = zsel; spar[g] = dec_score(key); }
        __syncthreads();
        const float r = tsrc * (1.0f / 64.0f);
        for (int i = hwg; i < 32; i += 4) {
            int   zp = zpar[i];
            float sp = spar[i];
            SCORE_ODD(zp, sp, r, i)
        }
        __syncthreads();
        // warp0 sorts the 32 odd keys desc
        unsigned long long okey = 0;
        if (g < 32) {
            okey = enc_key(sc_odd[lane], 2 * lane + 1);
            #pragma unroll
            for (int kk = 2; kk <= 32; kk <<= 1)
                #pragma unroll
                for (int j = kk >> 1; j > 0; j >>= 1) {
                    unsigned long long p = __shfl_xor_sync(0xffffffffu, okey, j);
                    bool mx = (((lane & j) == 0) == ((lane & kk) == 0));
                    okey = mx ? umax64(okey, p) : umin64(okey, p);
                }
            xkey[lane] = okey;
            // even child keeps parent score; new expanded idx = 2g
            key = (key & ~0xFFull) | (unsigned long long)(127 - 2 * g);
        }
        __syncthreads();
        if (g >= 32) key = xkey[63 - g];   // reversed odds -> bitonic 64
        __syncthreads();
        // 6-stage desc merge over 64 (order defines next level's tie-breaks)
        #pragma unroll
        for (int j = 32; j > 0; j >>= 1) {
            unsigned long long p;
            if (j == 32) { xkey[g] = key; __syncthreads(); p = xkey[g ^ 32]; __syncthreads(); }
            else          p = __shfl_xor_sync(0xffffffffu, key, j);
            bool mx = ((g & j) == 0);
            key = mx ? umax64(key, p) : umin64(key, p);
        }
        int e = 127 - (int)(key & 0xFFu);
        zsel = 2 * zpar[e >> 1] + (e & 1);
    }

    // ---------------- iterations 2..6: 64 parents -> top-64 of 128 -----------
    #pragma unroll 1
    for (int it = 2; it < 7; ++it) {
        __syncthreads();                  // protect zpar/spar read from prev iter
        zpar[g] = zsel;
        spar[g] = dec_score(key);
        __syncthreads();
        const float r = tsrc / (float)(32 << it);
        for (int i = hwg; i < 64; i += 4) {
            int   zp = zpar[i];
            float sp = spar[i];
            SCORE_ODD(zp, sp, r, i)
        }
        __syncthreads();

        // 21-stage desc bitonic sort of the 64 odd keys (2 warps)
        unsigned long long okey = enc_key(sc_odd[g], 2 * g + 1);
        #pragma unroll
        for (int kk = 2; kk <= 64; kk <<= 1)
            #pragma unroll
            for (int j = kk >> 1; j > 0; j >>= 1) {
                unsigned long long p;
                if (j == 32) { xkey[g] = okey; __syncthreads(); p = xkey[g ^ 32]; __syncthreads(); }
                else          p = __shfl_xor_sync(0xffffffffu, okey, j);
                bool mx = (((g & j) == 0) == ((g & kk) == 0));
                okey = mx ? umax64(okey, p) : umin64(okey, p);
            }

        // combine: evens (sorted desc, held in `key`) vs reversed odds
        xkey[g] = okey;
        key = (key & ~0xFFull) | (unsigned long long)(127 - 2 * g);  // even idx = 2g
        __syncthreads();
        key = umax64(key, xkey[63 - g]);   // top-64 multiset, bitonic sequence
        __syncthreads();
        // 6-stage desc merge -> sorted top-64. Skipped for the final level:
        // the epilogue (softmax + V gather) is order-invariant on the set.
        if (it < 6) {
            #pragma unroll
            for (int j = 32; j > 0; j >>= 1) {
                unsigned long long p;
                if (j == 32) { xkey[g] = key; __syncthreads(); p = xkey[g ^ 32]; __syncthreads(); }
                else          p = __shfl_xor_sync(0xffffffffu, key, j);
                bool mx = ((g & j) == 0);
                key = mx ? umax64(key, p) : umin64(key, p);
            }
        }
        int e = 127 - (int)(key & 0xFFu);
        zsel = 2 * zpar[e >> 1] + (e & 1);
    }

    // ---------------- final attention over the 64 kept candidates ------------
    {
        const float rf = tsrc * (1.0f / 2048.0f);
        int pos = min((int)rintf((float)zsel * rf), SS - 1);
        bool valid = ((float)pos < tsrc);
        float score = dec_score(key);
        float a = valid ? score * 0.125f : -1e9f;   // 1/sqrt(64)

        float m = a;
        m = fmaxf(m, __shfl_xor_sync(0xffffffffu, m, 16));
        m = fmaxf(m, __shfl_xor_sync(0xffffffffu, m, 8));
        m = fmaxf(m, __shfl_xor_sync(0xffffffffu, m, 4));
        m = fmaxf(m, __shfl_xor_sync(0xffffffffu, m, 2));
        m = fmaxf(m, __shfl_xor_sync(0xffffffffu, m, 1));
        if (lane == 0) red[g >> 5] = m;
        __syncthreads();
        m = fmaxf(red[0], red[1]);

        float e = valid ? expf(a - m) : 0.0f;   // invalid: ref exp underflows to 0
        float s = e;
        s += __shfl_xor_sync(0xffffffffu, s, 16);
        s += __shfl_xor_sync(0xffffffffu, s, 8);
        s += __shfl_xor_sync(0xffffffffu, s, 4);
        s += __shfl_xor_sync(0xffffffffu, s, 2);
        s += __shfl_xor_sync(0xffffffffu, s, 1);
        if (lane == 0) red[2 + (g >> 5)] = s;
        __syncthreads();
        s = red[2] + red[3];

        pvec[g]  = (s > 0.0f) ? (e / s) : 0.0f;  // all-invalid -> 0, matches ref
        pos_s[g] = pos;
        __syncthreads();

        // out[h] = sum_k p[k] * V[n, pos[k], h] ; thread g = h, coalesced loads
        const float* vb = v + (size_t)n * SS * HH + g;
        float acc = 0.0f;
        #pragma unroll 8
        for (int kk = 0; kk < KSEL; ++kk)
            acc = fmaf(pvec[kk], vb[(size_t)pos_s[kk] * HH], acc);
        out[((size_t)(n * TT + t)) * HH + g] = acc;
    }
    #undef SCORE_FRESH
    #undef SCORE_ODD
}

extern "C" void kernel_launch(void* const* d_in, const int* in_sizes, int n_in,
                              void* d_out, int out_size)
{
    const float* q = (const float*)d_in[0];
    const float* k = (const float*)d_in[1];
    const float* v = (const float*)d_in[2];
    float* out = (float*)d_out;
    (void)in_sizes; (void)n_in; (void)out_size;

    tree_attn_kernel<<<NBATCH * TT, 64>>>(q, k, v, out);
}

// round 8
// speedup vs baseline: 1.6297x; 1.6297x over previous
#include <cuda_runtime.h>
#include <stdint.h>

// Problem constants (fixed by the dataset)
#define NBATCH 16
#define TT     2048
#define SS     2048
#define HH     64
#define KSEL   64

__device__ __forceinline__ unsigned long long umax64(unsigned long long a, unsigned long long b) {
    return a > b ? a : b;
}
__device__ __forceinline__ unsigned long long umin64(unsigned long long a, unsigned long long b) {
    return a < b ? a : b;
}

// key = (sortable_score << 8) | (127 - expanded_idx)
// numeric DESC order == desc by score, ties broken by ascending index (lax.top_k)
__device__ __forceinline__ unsigned long long enc_key(float s, int idx) {
    unsigned int u  = __float_as_uint(s);
    unsigned int su = (u & 0x80000000u) ? ~u : (u | 0x80000000u);
    return ((unsigned long long)su << 8) | (unsigned long long)(127 - idx);
}

// inverse of enc_key's score field
__device__ __forceinline__ float dec_score(unsigned long long key) {
    unsigned int su = (unsigned int)(key >> 8);
    unsigned int u  = (su & 0x80000000u) ? (su & 0x7FFFFFFFu) : ~su;
    return __uint_as_float(u);
}

__global__ __launch_bounds__(64)
void tree_attn_kernel(const float* __restrict__ q,
                      const float* __restrict__ kmat,
                      const float* __restrict__ v,
                      float* __restrict__ out)
{
    __shared__ float              sc_odd[64];  // fresh (odd-child) scores
    __shared__ unsigned long long xkey[64];    // cross-warp sort exchange
    __shared__ int                zpar[64];    // parent z values
    __shared__ float              spar[64];    // parent scores
    __shared__ int                pos_s[64];
    __shared__ float              pvec[64];
    __shared__ float              red[4];

    const int row  = blockIdx.x;
    const int n    = row >> 11;
    const int t    = row & (TT - 1);
    const float tsrc = (float)(t + 1);

    const int g    = threadIdx.x;   // 0..63
    const int lane = g & 31;
    const int l16  = g & 15;
    const int hwg  = g >> 4;        // half-warp 0..3
    const unsigned gm = 0xFFFFu << (lane & 16);   // 16-lane group shfl mask

    const float* kbase = kmat + (size_t)n * SS * HH;
    const float4 q4 = ((const float4*)(q + ((size_t)(n * TT + t)) * HH))[l16];

    unsigned long long key = 0;  // selection key (score packed in bits [8,40))
    int zsel = 0;

    // R3-verbatim scoring reduction tree (numerics pinned: this tree's rounding
    // bit-matches the reference einsum; do NOT change the reduction order).
    #define SCORE_FRESH(POS, CIDX)                                            \
        {                                                                     \
            const float4* krow = (const float4*)(kbase + (size_t)(POS) * HH); \
            float4 k4 = krow[l16];                                            \
            float part = q4.x * k4.x + q4.y * k4.y + q4.z * k4.z + q4.w * k4.w;\
            part += __shfl_xor_sync(gm, part, 1);                             \
            part += __shfl_xor_sync(gm, part, 2);                             \
            part += __shfl_xor_sync(gm, part, 4);                             \
            part += __shfl_xor_sync(gm, part, 8);                             \
            if (l16 == 0) sc_odd[CIDX] = part;                                \
        }

    // Odd child vs even sibling: if both round to the same token, the fresh
    // score would be bit-equal to the parent's score -> reuse, skip LDG+SHFL.
    #define SCORE_ODD(ZP, SP, R, CIDX)                                        \
        {                                                                     \
            int posO = min((int)rintf((float)(2 * (ZP) + 1) * (R)), SS - 1);  \
            int posE = min((int)rintf((float)(2 * (ZP)) * (R)), SS - 1);      \
            if (posO == posE) {                                               \
                if (l16 == 0) sc_odd[CIDX] = (SP);                            \
            } else {                                                          \
                SCORE_FRESH(posO, CIDX)                                       \
            }                                                                 \
        }

    // ---------------- iteration 0: 32 fresh candidates, w2=32 ----------------
    {
        const float r = tsrc * (1.0f / 32.0f);
        for (int c = hwg; c < 32; c += 4) {
            int pos = min((int)rintf((float)c * r), SS - 1);
            SCORE_FRESH(pos, c)
        }
        __syncthreads();
        if (g < 32) {   // warp0: 15-stage desc bitonic sort of 32
            key = enc_key(sc_odd[lane], lane);   // expanded idx == z at level 0
            #pragma unroll
            for (int kk = 2; kk <= 32; kk <<= 1)
                #pragma unroll
                for (int j = kk >> 1; j > 0; j >>= 1) {
                    unsigned long long p = __shfl_xor_sync(0xffffffffu, key, j);
                    bool mx = (((lane & j) == 0) == ((lane & kk) == 0));
                    key = mx ? umax64(key, p) : umin64(key, p);
                }
            zsel = 127 - (int)(key & 0xFFu);
        }
        __syncthreads();   // sc_odd reuse barrier
    }

    // ---------------- iteration 1: 32 parents -> keep all 64, w2=64 ----------
    {
        if (g < 32) { zpar[g] = zsel; spar[g] = dec_score(key); }
        __syncthreads();
        const float r = tsrc * (1.0f / 64.0f);
        for (int i = hwg; i < 32; i += 4) {
            int   zp = zpar[i];
            float sp = spar[i];
            SCORE_ODD(zp, sp, r, i)
        }
        __syncthreads();
        // warp0 sorts the 32 odd keys desc
        unsigned long long okey = 0;
        if (g < 32) {
            okey = enc_key(sc_odd[lane], 2 * lane + 1);
            #pragma unroll
            for (int kk = 2; kk <= 32; kk <<= 1)
                #pragma unroll
                for (int j = kk >> 1; j > 0; j >>= 1) {
                    unsigned long long p = __shfl_xor_sync(0xffffffffu, okey, j);
                    bool mx = (((lane & j) == 0) == ((lane & kk) == 0));
                    okey = mx ? umax64(okey, p) : umin64(okey, p);
                }
            xkey[lane] = okey;
            // even child keeps parent score; new expanded idx = 2g
            key = (key & ~0xFFull) | (unsigned long long)(127 - 2 * g);
        }
        __syncthreads();
        if (g >= 32) key = xkey[63 - g];   // reversed odds -> bitonic 64
        __syncthreads();
        // 6-stage desc merge over 64 (order defines next level's tie-breaks)
        #pragma unroll
        for (int j = 32; j > 0; j >>= 1) {
            unsigned long long p;
            if (j == 32) { xkey[g] = key; __syncthreads(); p = xkey[g ^ 32]; __syncthreads(); }
            else          p = __shfl_xor_sync(0xffffffffu, key, j);
            bool mx = ((g & j) == 0);
            key = mx ? umax64(key, p) : umin64(key, p);
        }
        int e = 127 - (int)(key & 0xFFu);
        zsel = 2 * zpar[e >> 1] + (e & 1);
    }

    // ---------------- iterations 2..6: 64 parents -> top-64 of 128 -----------
    #pragma unroll 1
    for (int it = 2; it < 7; ++it) {
        __syncthreads();                  // protect zpar/spar read from prev iter
        zpar[g] = zsel;
        spar[g] = dec_score(key);
        __syncthreads();
        const float r = tsrc / (float)(32 << it);
        for (int i = hwg; i < 64; i += 4) {
            int   zp = zpar[i];
            float sp = spar[i];
            SCORE_ODD(zp, sp, r, i)
        }
        __syncthreads();

        // 21-stage desc bitonic sort of the 64 odd keys (2 warps)
        unsigned long long okey = enc_key(sc_odd[g], 2 * g + 1);
        #pragma unroll
        for (int kk = 2; kk <= 64; kk <<= 1)
            #pragma unroll
            for (int j = kk >> 1; j > 0; j >>= 1) {
                unsigned long long p;
                if (j == 32) { xkey[g] = okey; __syncthreads(); p = xkey[g ^ 32]; __syncthreads(); }
                else          p = __shfl_xor_sync(0xffffffffu, okey, j);
                bool mx = (((g & j) == 0) == ((g & kk) == 0));
                okey = mx ? umax64(okey, p) : umin64(okey, p);
            }

        // combine: evens (sorted desc, held in `key`) vs reversed odds
        xkey[g] = okey;
        key = (key & ~0xFFull) | (unsigned long long)(127 - 2 * g);  // even idx = 2g
        __syncthreads();
        key = umax64(key, xkey[63 - g]);   // top-64 multiset, bitonic sequence
        __syncthreads();
        // 6-stage desc merge -> sorted top-64. Skipped for the final level:
        // the epilogue (softmax + V gather) is order-invariant on the set.
        if (it < 6) {
            #pragma unroll
            for (int j = 32; j > 0; j >>= 1) {
                unsigned long long p;
                if (j == 32) { xkey[g] = key; __syncthreads(); p = xkey[g ^ 32]; __syncthreads(); }
                else          p = __shfl_xor_sync(0xffffffffu, key, j);
                bool mx = ((g & j) == 0);
                key = mx ? umax64(key, p) : umin64(key, p);
            }
        }
        int e = 127 - (int)(key & 0xFFu);
        zsel = 2 * zpar[e >> 1] + (e & 1);
    }

    // ---------------- final attention over the 64 kept candidates ------------
    {
        const float rf = tsrc * (1.0f / 2048.0f);
        int pos = min((int)rintf((float)zsel * rf), SS - 1);
        bool valid = ((float)pos < tsrc);
        float score = dec_score(key);
        float a = valid ? score * 0.125f : -1e9f;   // 1/sqrt(64)

        float m = a;
        m = fmaxf(m, __shfl_xor_sync(0xffffffffu, m, 16));
        m = fmaxf(m, __shfl_xor_sync(0xffffffffu, m, 8));
        m = fmaxf(m, __shfl_xor_sync(0xffffffffu, m, 4));
        m = fmaxf(m, __shfl_xor_sync(0xffffffffu, m, 2));
        m = fmaxf(m, __shfl_xor_sync(0xffffffffu, m, 1));
        if (lane == 0) red[g >> 5] = m;
        __syncthreads();
        m = fmaxf(red[0], red[1]);

        float e = valid ? expf(a - m) : 0.0f;   // invalid: ref exp underflows to 0
        float s = e;
        s += __shfl_xor_sync(0xffffffffu, s, 16);
        s += __shfl_xor_sync(0xffffffffu, s, 8);
        s += __shfl_xor_sync(0xffffffffu, s, 4);
        s += __shfl_xor_sync(0xffffffffu, s, 2);
        s += __shfl_xor_sync(0xffffffffu, s, 1);
        if (lane == 0) red[2 + (g >> 5)] = s;
        __syncthreads();
        s = red[2] + red[3];

        pvec[g]  = (s > 0.0f) ? (e / s) : 0.0f;  // all-invalid -> 0, matches ref
        pos_s[g] = pos;
        __syncthreads();

        // out[h] = sum_k p[k] * V[n, pos[k], h] ; thread g = h, coalesced loads
        const float* vb = v + (size_t)n * SS * HH + g;
        float acc = 0.0f;
        #pragma unroll 8
        for (int kk = 0; kk < KSEL; ++kk)
            acc = fmaf(pvec[kk], vb[(size_t)pos_s[kk] * HH], acc);
        out[((size_t)(n * TT + t)) * HH + g] = acc;
    }
    #undef SCORE_FRESH
    #undef SCORE_ODD
}

extern "C" void kernel_launch(void* const* d_in, const int* in_sizes, int n_in,
                              void* d_out, int out_size)
{
    const float* q = (const float*)d_in[0];
    const float* k = (const float*)d_in[1];
    const float* v = (const float*)d_in[2];
    float* out = (float*)d_out;
    (void)in_sizes; (void)n_in; (void)out_size;

    tree_attn_kernel<<<NBATCH * TT, 64>>>(q, k, v, out);
}